// round 2
// baseline (speedup 1.0000x reference)
#include <cuda_runtime.h>
#include <cuda_bf16.h>
#include <cstdint>
#include <cstddef>

// ============================================================================
// BitLinear via int8 IMMA (mma.sync - works on plain sm_103 target):
//   out[m,n] = (sum_k qx[m,k]*t[n,k]) * s_tok[m] * s_w
//   qx in [-8,7] int8, t in {-1,0,1} int8. int32 accumulation is exact.
// ============================================================================

static constexpr int MDIM = 8192;
static constexpr int NDIM = 16384;
static constexpr int KDIM = 4096;
static constexpr float EPSV = 1e-5f;

__device__ __align__(128) int8_t g_qx[(size_t)MDIM * KDIM];   // 33.5 MB
__device__ __align__(128) int8_t g_wq[(size_t)NDIM * KDIM];   // 67 MB
__device__ float g_st[MDIM];                                  // s_tok * s_w
__device__ float g_partial[2048];
__device__ float g_wscale;

__device__ __forceinline__ uint32_t smem_u32(const void* p) {
    uint32_t a;
    asm("{ .reg .u64 t; cvta.to.shared.u64 t, %1; cvt.u32.u64 %0, t; }" : "=r"(a) : "l"(p));
    return a;
}

// ---------------------------------------------------------------------------
// Weight scale: two-pass deterministic mean(|w|)
// ---------------------------------------------------------------------------
__global__ void wsum_kernel(const float* __restrict__ w) {
    __shared__ float red[256];
    const float4* w4 = reinterpret_cast<const float4*>(w);
    const size_t n4 = (size_t)NDIM * KDIM / 4;
    float s = 0.f;
    for (size_t i = (size_t)blockIdx.x * 256 + threadIdx.x; i < n4; i += (size_t)2048 * 256) {
        float4 v = w4[i];
        s += fabsf(v.x) + fabsf(v.y) + fabsf(v.z) + fabsf(v.w);
    }
    red[threadIdx.x] = s;
    __syncthreads();
    for (int off = 128; off > 0; off >>= 1) {
        if (threadIdx.x < off) red[threadIdx.x] += red[threadIdx.x + off];
        __syncthreads();
    }
    if (threadIdx.x == 0) g_partial[blockIdx.x] = red[0];
}

__global__ void wscale_kernel() {
    __shared__ float red[1024];
    red[threadIdx.x] = g_partial[threadIdx.x] + g_partial[threadIdx.x + 1024];
    __syncthreads();
    for (int off = 512; off > 0; off >>= 1) {
        if (threadIdx.x < off) red[threadIdx.x] += red[threadIdx.x + off];
        __syncthreads();
    }
    if (threadIdx.x == 0)
        g_wscale = fmaxf(red[0] / (float)((size_t)NDIM * KDIM), EPSV);
}

// ---------------------------------------------------------------------------
// Weight ternarize -> int8 {-1,0,1}  (4 floats -> 4 bytes per iter)
// ---------------------------------------------------------------------------
__global__ void wquant_kernel(const float* __restrict__ w) {
    const float inv = 1.0f / g_wscale;
    const float4* w4 = reinterpret_cast<const float4*>(w);
    uchar4* o4 = reinterpret_cast<uchar4*>(g_wq);
    const size_t n4 = (size_t)NDIM * KDIM / 4;
    for (size_t i = (size_t)blockIdx.x * blockDim.x + threadIdx.x; i < n4;
         i += (size_t)gridDim.x * blockDim.x) {
        float4 v = w4[i];
        // note: reference divides; scale>0 so x/s == x*(1/s) differs only at ulp
        // ties; round-to-even on /scale. Use true division for exactness.
        float sc = g_wscale;
        int a = (int)fminf(fmaxf(rintf(v.x / sc), -1.f), 1.f);
        int b = (int)fminf(fmaxf(rintf(v.y / sc), -1.f), 1.f);
        int c = (int)fminf(fmaxf(rintf(v.z / sc), -1.f), 1.f);
        int d = (int)fminf(fmaxf(rintf(v.w / sc), -1.f), 1.f);
        o4[i] = make_uchar4((uint8_t)(int8_t)a, (uint8_t)(int8_t)b,
                            (uint8_t)(int8_t)c, (uint8_t)(int8_t)d);
        (void)inv;
    }
}

// ---------------------------------------------------------------------------
// Activation quant: per-token absmax -> int8 in [-8,7]
// One block per token (4096 elems, 256 threads x 16).
// ---------------------------------------------------------------------------
__global__ void xquant_kernel(const float* __restrict__ x) {
    __shared__ float red[256];
    __shared__ float s_sh;
    const int t = blockIdx.x;
    const float4* xr = reinterpret_cast<const float4*>(x + (size_t)t * KDIM);
    float4 v[4];
    float mx = 0.f;
#pragma unroll
    for (int j = 0; j < 4; j++) {
        v[j] = xr[j * 256 + threadIdx.x];
        mx = fmaxf(mx, fmaxf(fmaxf(fabsf(v[j].x), fabsf(v[j].y)),
                             fmaxf(fabsf(v[j].z), fabsf(v[j].w))));
    }
    red[threadIdx.x] = mx;
    __syncthreads();
    for (int off = 128; off > 0; off >>= 1) {
        if (threadIdx.x < off) red[threadIdx.x] = fmaxf(red[threadIdx.x], red[threadIdx.x + off]);
        __syncthreads();
    }
    if (threadIdx.x == 0) {
        float s = fmaxf(red[0], EPSV) / 7.0f;
        s_sh = s;
        g_st[t] = s * g_wscale;
    }
    __syncthreads();
    const float s = s_sh;
    uchar4* o4 = reinterpret_cast<uchar4*>(g_qx + (size_t)t * KDIM);
#pragma unroll
    for (int j = 0; j < 4; j++) {
        int i4 = j * 256 + threadIdx.x;
        int a = (int)fminf(fmaxf(rintf(v[j].x / s), -8.f), 7.f);
        int b = (int)fminf(fmaxf(rintf(v[j].y / s), -8.f), 7.f);
        int c = (int)fminf(fmaxf(rintf(v[j].z / s), -8.f), 7.f);
        int d = (int)fminf(fmaxf(rintf(v[j].w / s), -8.f), 7.f);
        o4[i4] = make_uchar4((uint8_t)(int8_t)a, (uint8_t)(int8_t)b,
                             (uint8_t)(int8_t)c, (uint8_t)(int8_t)d);
    }
}

// ---------------------------------------------------------------------------
// GEMM: out[8192,16384] = qx[8192,4096](s8) @ wq[16384,4096](s8)^T, scaled.
// BM=BN=128, BK=64 (bytes), 4-stage cp.async, 8 warps 2(M)x4(N),
// warp tile 64x32, mma.m16n8k32.s8. SMEM rows 64B, XOR-16B-chunk swizzle.
// ---------------------------------------------------------------------------
static constexpr int BM = 128, BN = 128, BK = 64, STAGES = 4;
static constexpr int KT = KDIM / BK;          // 64 iters
static constexpr int STAGE_BYTES = BM * BK + BN * BK;   // 16384
static constexpr int SMEM_TOTAL = STAGES * STAGE_BYTES; // 65536

// phys chunk = chunk ^ ((row>>1)&3); offset = row*64 + phys*16
__device__ __forceinline__ uint32_t swz(int row, int chunk) {
    return (uint32_t)(row * 64 + ((chunk ^ ((row >> 1) & 3)) << 4));
}

#define LDSM_X4(R0, R1, R2, R3, ADDR)                                          \
    asm volatile("ldmatrix.sync.aligned.m8n8.x4.shared.b16 {%0,%1,%2,%3}, [%4];" \
                 : "=r"(R0), "=r"(R1), "=r"(R2), "=r"(R3) : "r"(ADDR))

#define MMA_S8(C, A, B0, B1)                                                   \
    asm volatile(                                                              \
        "mma.sync.aligned.m16n8k32.row.col.s32.s8.s8.s32 "                     \
        "{%0,%1,%2,%3}, {%4,%5,%6,%7}, {%8,%9}, {%0,%1,%2,%3};"                \
        : "+r"((C)[0]), "+r"((C)[1]), "+r"((C)[2]), "+r"((C)[3])               \
        : "r"((A)[0]), "r"((A)[1]), "r"((A)[2]), "r"((A)[3]), "r"(B0), "r"(B1))

__global__ void __launch_bounds__(256, 2)
gemm_kernel(float* __restrict__ out) {
    extern __shared__ char smem[];
    const uint32_t sb = smem_u32(smem);
    const int tid = threadIdx.x;
    const int wid = tid >> 5;
    const int lane = tid & 31;
    const int warp_m = wid >> 2;   // 0..1
    const int warp_n = wid & 3;    // 0..3

    // GROUP_M=8 rasterization
    const int num_n = NDIM / BN;   // 128
    int pid = blockIdx.x;
    int group = pid / (8 * num_n);
    int pid_m = group * 8 + (pid % 8);
    int pid_n = (pid % (8 * num_n)) / 8;
    const int m_base = pid_m * BM;
    const int n_base = pid_n * BN;

    // ---- global->smem load slots: thread handles row = tid>>1, 2 chunks ----
    const int lrow = tid >> 1;
    const int lc = (tid & 1) * 2;
    const int8_t* ga = g_qx + (size_t)(m_base + lrow) * KDIM + lc * 16;
    const int8_t* gb = g_wq + (size_t)(n_base + lrow) * KDIM + lc * 16;
    const uint32_t sa0 = swz(lrow, lc), sa1 = swz(lrow, lc + 1);

    auto load_tile = [&](int s, int k) {
        const uint32_t st = sb + s * STAGE_BYTES;
        const int8_t* a = ga + k * BK;
        const int8_t* b = gb + k * BK;
        asm volatile("cp.async.cg.shared.global [%0], [%1], 16;" :: "r"(st + sa0), "l"(a) : "memory");
        asm volatile("cp.async.cg.shared.global [%0], [%1], 16;" :: "r"(st + sa1), "l"(a + 16) : "memory");
        asm volatile("cp.async.cg.shared.global [%0], [%1], 16;" :: "r"(st + BM * BK + sa0), "l"(b) : "memory");
        asm volatile("cp.async.cg.shared.global [%0], [%1], 16;" :: "r"(st + BM * BK + sa1), "l"(b + 16) : "memory");
        asm volatile("cp.async.commit_group;" ::: "memory");
    };

    // ---- ldmatrix per-lane address components ----
    const int ra = (lane & 7) + ((lane >> 3) & 1) * 8;  // row within 16-row atom
    const int csel = lane >> 4;                          // 0/1: which 16B chunk

    // A atoms: rows warp_m*64 + i*16 + ra
    uint32_t a_rowterm[4]; int a_swz[4];
#pragma unroll
    for (int i = 0; i < 4; i++) {
        int r = warp_m * 64 + i * 16 + ra;
        a_rowterm[i] = (uint32_t)(r * 64);
        a_swz[i] = (r >> 1) & 3;
    }
    // B atom-pairs: rows warp_n*32 + j*16 + ra
    uint32_t b_rowterm[2]; int b_swz[2];
#pragma unroll
    for (int j = 0; j < 2; j++) {
        int r = warp_n * 32 + j * 16 + ra;
        b_rowterm[j] = (uint32_t)(BM * BK + r * 64);
        b_swz[j] = (r >> 1) & 3;
    }

    int acc[4][4][4];
#pragma unroll
    for (int i = 0; i < 4; i++)
#pragma unroll
        for (int j = 0; j < 4; j++)
#pragma unroll
            for (int c = 0; c < 4; c++) acc[i][j][c] = 0;

    // ---- prologue ----
    load_tile(0, 0);
    load_tile(1, 1);
    load_tile(2, 2);

    for (int k = 0; k < KT; k++) {
        asm volatile("cp.async.wait_group 2;" ::: "memory");
        __syncthreads();

        // issue next stage (uniform commit count so wait_group 2 is exact)
        if (k + 3 < KT) load_tile((k + 3) & 3, k + 3);
        else asm volatile("cp.async.commit_group;" ::: "memory");

        const uint32_t st = sb + (k & 3) * STAGE_BYTES;
#pragma unroll
        for (int ks = 0; ks < 2; ks++) {
            const int cbase = ks * 2 + csel;
            uint32_t afr[4][4];
#pragma unroll
            for (int i = 0; i < 4; i++) {
                uint32_t addr = st + a_rowterm[i] + (uint32_t)((cbase ^ a_swz[i]) << 4);
                LDSM_X4(afr[i][0], afr[i][1], afr[i][2], afr[i][3], addr);
            }
            uint32_t bfr[2][4];  // [pair][{b0_n0,b0_n1,b1_n0,b1_n1}]
#pragma unroll
            for (int j = 0; j < 2; j++) {
                uint32_t addr = st + b_rowterm[j] + (uint32_t)((cbase ^ b_swz[j]) << 4);
                LDSM_X4(bfr[j][0], bfr[j][1], bfr[j][2], bfr[j][3], addr);
            }
#pragma unroll
            for (int i = 0; i < 4; i++) {
#pragma unroll
                for (int j = 0; j < 2; j++) {
                    MMA_S8(acc[i][2 * j],     afr[i], bfr[j][0], bfr[j][2]);
                    MMA_S8(acc[i][2 * j + 1], afr[i], bfr[j][1], bfr[j][3]);
                }
            }
        }
    }

    // ---- epilogue: int32 -> f32 * s_tok*s_w, direct f32x2 stores ----
#pragma unroll
    for (int i = 0; i < 4; i++) {
        const int r0 = m_base + warp_m * 64 + i * 16 + (lane >> 2);
        const int r1 = r0 + 8;
        const float st0 = g_st[r0];
        const float st1 = g_st[r1];
        float* o0 = out + (size_t)r0 * NDIM + n_base + warp_n * 32 + (lane & 3) * 2;
        float* o1 = out + (size_t)r1 * NDIM + n_base + warp_n * 32 + (lane & 3) * 2;
#pragma unroll
        for (int j = 0; j < 4; j++) {
            float2 v0 = make_float2((float)acc[i][j][0] * st0, (float)acc[i][j][1] * st0);
            float2 v1 = make_float2((float)acc[i][j][2] * st1, (float)acc[i][j][3] * st1);
            *reinterpret_cast<float2*>(o0 + j * 8) = v0;
            *reinterpret_cast<float2*>(o1 + j * 8) = v1;
        }
    }
}

// ---------------------------------------------------------------------------
extern "C" void kernel_launch(void* const* d_in, const int* in_sizes, int n_in,
                              void* d_out, int out_size) {
    const float* x = (const float*)d_in[0];
    const float* w = (const float*)d_in[1];
    if (n_in >= 2 && in_sizes[0] > in_sizes[1]) {  // x is 33.5M elems, w is 67M
        const float* t = x; x = w; w = t;
    }
    float* out = (float*)d_out;

    wsum_kernel<<<2048, 256>>>(w);
    wscale_kernel<<<1, 1024>>>();
    wquant_kernel<<<8192, 256>>>(w);
    xquant_kernel<<<MDIM, 256>>>(x);

    static bool attr_set = false;
    if (!attr_set) {
        cudaFuncSetAttribute(gemm_kernel, cudaFuncAttributeMaxDynamicSharedMemorySize, SMEM_TOTAL);
        attr_set = true;
    }
    gemm_kernel<<<(MDIM / BM) * (NDIM / BN), 256, SMEM_TOTAL>>>(out);
}